// round 14
// baseline (speedup 1.0000x reference)
#include <cuda_runtime.h>
#include <cstdint>

// out[e, 0:128]   = node_states[src[e], :]
// out[e, 128:256] = node_states[tgt[e], :]
// Final config (R12 measured best, 49.34us): 2 edges/warp, block 256,
// evict_last gathers (createpolicy + cache_hint), evict-first (__stcs) stores.
// This round adds evict-first (__ldcs) on the single-touch index stream —
// the last byte stream at default policy — completing the L2 policy scheme:
//   node_states (5.12 MB, ~64x reuse)  -> evict_last  (pinned)
//   indices     (2.6 MB, single touch) -> evict_first (transient)
//   output      (328 MB, never re-read)-> evict_first (prompt drain)
// Measured ladder: stores .cs 49.6 < .wt 51.6 < default 53.3; +evict_last
// loads -> 49.34. Binder: mandatory 328 MB HBM write stream at ~6.64 TB/s
// effective (~83% of 8 TB/s spec) — practical floor for this access mix.

__device__ __forceinline__ float4 ldg_evict_last(const float4* p, uint64_t pol) {
    float4 v;
    asm volatile("ld.global.nc.L2::cache_hint.v4.b32 {%0,%1,%2,%3}, [%4], %5;"
        : "=f"(v.x), "=f"(v.y), "=f"(v.z), "=f"(v.w)
        : "l"(p), "l"(pol));
    return v;
}

__global__ __launch_bounds__(256) void node_propagate_kernel(
    const float4* __restrict__ ns,   // [N_NODES, 32] as float4
    const int* __restrict__ src,     // [E] int32
    const int* __restrict__ tgt,     // [E] int32
    float4* __restrict__ out,        // [E, 64] as float4
    int nPairs)                      // E/2
{
    const int gwarp = (int)((blockIdx.x * (unsigned)blockDim.x + threadIdx.x) >> 5);
    const int lane  = threadIdx.x & 31;
    if (gwarp >= nPairs) return;
    const int e0 = gwarp * 2;

    // evict_last policy for the reused gather set.
    uint64_t pol;
    asm("createpolicy.fractional.L2::evict_last.b64 %0, 1.0;" : "=l"(pol));

    // Index pairs: single-touch stream -> evict-first loads.
    const int2 s2 = __ldcs((const int2*)(src + e0));
    const int2 t2 = __ldcs((const int2*)(tgt + e0));

    // 4 independent gathers in flight; evict_last pins rows in L2.
    const float4 a0 = ldg_evict_last(&ns[(size_t)s2.x * 32 + lane], pol);
    const float4 b0 = ldg_evict_last(&ns[(size_t)t2.x * 32 + lane], pol);
    const float4 a1 = ldg_evict_last(&ns[(size_t)s2.y * 32 + lane], pol);
    const float4 b1 = ldg_evict_last(&ns[(size_t)t2.y * 32 + lane], pol);

    // Evict-first stores: prompt full-line drain, protect the gather set.
    float4* o = out + (size_t)e0 * 64;
    __stcs(o +      lane, a0);
    __stcs(o + 32 + lane, b0);
    __stcs(o + 64 + lane, a1);
    __stcs(o + 96 + lane, b1);
}

// Tail for odd E (unused for E=320000).
__global__ void node_propagate_tail(
    const float4* __restrict__ ns,
    const int* __restrict__ src,
    const int* __restrict__ tgt,
    float4* __restrict__ out,
    int e)
{
    const int lane = threadIdx.x & 31;
    const int s = __ldg(&src[e]);
    const int t = __ldg(&tgt[e]);
    const float4 a = __ldg(&ns[(size_t)s * 32 + lane]);
    const float4 b = __ldg(&ns[(size_t)t * 32 + lane]);
    float4* o = out + (size_t)e * 64;
    __stcs(o + lane,      a);
    __stcs(o + 32 + lane, b);
}

extern "C" void kernel_launch(void* const* d_in, const int* in_sizes, int n_in,
                              void* d_out, int out_size)
{
    const float4* ns  = (const float4*)d_in[0];
    const int*    src = (const int*)d_in[1];
    const int*    tgt = (const int*)d_in[2];
    float4*       out = (float4*)d_out;

    const int E      = in_sizes[1];   // 320000 edges
    const int nPairs = E / 2;

    const int threads = 256;          // 8 warps -> 16 edges per block
    const int blocks  = (nPairs * 32 + threads - 1) / threads;

    node_propagate_kernel<<<blocks, threads>>>(ns, src, tgt, out, nPairs);

    if (E & 1)
        node_propagate_tail<<<1, 32>>>(ns, src, tgt, out, E - 1);
}

// round 15
// speedup vs baseline: 1.0546x; 1.0546x over previous
#include <cuda_runtime.h>
#include <cstdint>

// FINAL (R12 measured best: 49.34us, resubmitted for revalidation).
// out[e, 0:128]   = node_states[src[e], :]
// out[e, 128:256] = node_states[tgt[e], :]
//
// Config: one warp per TWO edges, block 256, int2 broadcast index loads
// (default policy — R14 showed evict-first idx loads regress: index lines are
// shared across warps), L2::evict_last on the node_states gathers (pins the
// 5.12 MB / ~64x-reused set), evict-first (__stcs) output stores (prompt
// full-line drain of the 328 MB write stream).
//
// Measured ladder: stores .cs 49.6 < .wt 51.6 < default 53.3; +evict_last
// gathers -> 49.34. All structural alternatives (MLP 2/4/8, blk 128/512,
// TMA bulk store, persistent grid, 256-bit accesses) measured neutral or
// worse. Binder: mandatory 328 MB HBM write stream at ~6.64 TB/s effective
// (~83% of 8 TB/s spec) — the practical floor for this access mix.

__device__ __forceinline__ float4 ldg_evict_last(const float4* p, uint64_t pol) {
    float4 v;
    asm volatile("ld.global.nc.L2::cache_hint.v4.b32 {%0,%1,%2,%3}, [%4], %5;"
        : "=f"(v.x), "=f"(v.y), "=f"(v.z), "=f"(v.w)
        : "l"(p), "l"(pol));
    return v;
}

__global__ __launch_bounds__(256) void node_propagate_kernel(
    const float4* __restrict__ ns,   // [N_NODES, 32] as float4
    const int* __restrict__ src,     // [E] int32
    const int* __restrict__ tgt,     // [E] int32
    float4* __restrict__ out,        // [E, 64] as float4
    int nPairs)                      // E/2
{
    const int gwarp = (int)((blockIdx.x * (unsigned)blockDim.x + threadIdx.x) >> 5);
    const int lane  = threadIdx.x & 31;
    if (gwarp >= nPairs) return;
    const int e0 = gwarp * 2;

    // evict_last policy for the reused gather set.
    uint64_t pol;
    asm("createpolicy.fractional.L2::evict_last.b64 %0, 1.0;" : "=l"(pol));

    // Index pairs: adjacent int32s -> one 8B broadcast load each (default
    // policy: lines are shared across warps, evict-first regressed in R14).
    const int2 s2 = *(const int2*)(src + e0);
    const int2 t2 = *(const int2*)(tgt + e0);

    // 4 independent gathers in flight; evict_last pins rows in L2.
    const float4 a0 = ldg_evict_last(&ns[(size_t)s2.x * 32 + lane], pol);
    const float4 b0 = ldg_evict_last(&ns[(size_t)t2.x * 32 + lane], pol);
    const float4 a1 = ldg_evict_last(&ns[(size_t)s2.y * 32 + lane], pol);
    const float4 b1 = ldg_evict_last(&ns[(size_t)t2.y * 32 + lane], pol);

    // Evict-first stores: prompt full-line drain, protect the gather set.
    float4* o = out + (size_t)e0 * 64;
    __stcs(o +      lane, a0);
    __stcs(o + 32 + lane, b0);
    __stcs(o + 64 + lane, a1);
    __stcs(o + 96 + lane, b1);
}

// Tail for odd E (unused for E=320000).
__global__ void node_propagate_tail(
    const float4* __restrict__ ns,
    const int* __restrict__ src,
    const int* __restrict__ tgt,
    float4* __restrict__ out,
    int e)
{
    const int lane = threadIdx.x & 31;
    const int s = __ldg(&src[e]);
    const int t = __ldg(&tgt[e]);
    const float4 a = __ldg(&ns[(size_t)s * 32 + lane]);
    const float4 b = __ldg(&ns[(size_t)t * 32 + lane]);
    float4* o = out + (size_t)e * 64;
    __stcs(o + lane,      a);
    __stcs(o + 32 + lane, b);
}

extern "C" void kernel_launch(void* const* d_in, const int* in_sizes, int n_in,
                              void* d_out, int out_size)
{
    const float4* ns  = (const float4*)d_in[0];
    const int*    src = (const int*)d_in[1];
    const int*    tgt = (const int*)d_in[2];
    float4*       out = (float4*)d_out;

    const int E      = in_sizes[1];   // 320000 edges
    const int nPairs = E / 2;

    const int threads = 256;          // 8 warps -> 16 edges per block
    const int blocks  = (nPairs * 32 + threads - 1) / threads;

    node_propagate_kernel<<<blocks, threads>>>(ns, src, tgt, out, nPairs);

    if (E & 1)
        node_propagate_tail<<<1, 32>>>(ns, src, tgt, out, E - 1);
}